// round 10
// baseline (speedup 1.0000x reference)
#include <cuda_runtime.h>
#include <cuda_bf16.h>
#include <float.h>

#define NEXP 64
#define TPB  256

#define FMA2(d, a, b, c) \
    asm("fma.rn.f32x2 %0, %1, %2, %3;" : "=l"(d) : "l"(a), "l"(b), "l"(c))
#define PACK2(d, lo, hi) \
    asm("mov.b64 %0, {%1, %2};" : "=l"(d) : "f"(lo), "f"(hi))
#define UNPACK2(lo, hi, s) \
    asm("mov.b64 {%0, %1}, %2;" : "=f"(lo), "=f"(hi) : "l"(s))

// Rare exact path: faithful reproduction of the reference fp32 sequence
// (sqrt logits + softmax-tie band). __noinline__ + partial unroll so it never
// inflates the main kernel's register count (R3 lesson: inlining -> 255 regs).
__device__ __noinline__ int exact_argmax(float px, float py, float pz,
                                         const float4* __restrict__ sc)
{
    float m = -FLT_MAX;
    #pragma unroll 4
    for (int e = 0; e < NEXP; e++) {
        float4 c = sc[e];
        float dx = __fsub_rn(px, c.x);
        float dy = __fsub_rn(py, c.y);
        float dz = __fsub_rn(pz, c.z);
        float d2 = __fadd_rn(__fadd_rn(__fmul_rn(dx, dx), __fmul_rn(dy, dy)),
                             __fmul_rn(dz, dz));
        float dist = __fsqrt_rn(__fadd_rn(d2, 1e-12f));
        float li   = __fmul_rn(10.0f, __fsub_rn(c.w, dist));
        if (li > m) m = li;
    }
    // softmax tie band: exp(l-m) rounds to 1.0f when (m-l) <= 2^-25, so
    // argmax(softmax) picks the FIRST index inside that band.
    const float band = 2.9802322e-8f;  // 2^-25
    #pragma unroll 4
    for (int e = 0; e < NEXP; e++) {
        float4 c = sc[e];
        float dx = __fsub_rn(px, c.x);
        float dy = __fsub_rn(py, c.y);
        float dz = __fsub_rn(pz, c.z);
        float d2 = __fadd_rn(__fadd_rn(__fmul_rn(dx, dx), __fmul_rn(dy, dy)),
                             __fmul_rn(dz, dz));
        float dist = __fsqrt_rn(__fadd_rn(d2, 1e-12f));
        float li   = __fmul_rn(10.0f, __fsub_rn(c.w, dist));
        if (__fsub_rn(m, li) <= band) return e;
    }
    return NEXP - 1;  // unreachable
}

__global__ void __launch_bounds__(TPB)
optix_route_fused(const float* __restrict__ pos,
                  const float* __restrict__ centers,
                  const float* __restrict__ radii,
                  float* __restrict__ out_probs,
                  float* __restrict__ out_ids,
                  int B, int write_ids)
{
    __shared__ float4 sraw[NEXP];        // (cx, cy, cz, safe_r) -- exact path
    // pair-interleaved dot tables for f32x2: for pair j (experts 2j, 2j+1):
    //   sA[j] = (cx'_{2j}, cx'_{2j+1}, cy'_{2j}, cy'_{2j+1})
    //   sB[j] = (cz'_{2j}, cz'_{2j+1}, c2_{2j},  c2_{2j+1})   (c' = -2c)
    __shared__ float4 sA[NEXP / 2];
    __shared__ float4 sB[NEXP / 2];
    __shared__ int    sids[TPB];
    __shared__ int    s_uniform;
    __shared__ float  s_maxc2;

    const int tid = threadIdx.x;

    if (tid < NEXP) {
        float cx = centers[3 * tid + 0];
        float cy = centers[3 * tid + 1];
        float cz = centers[3 * tid + 2];
        float r  = fmaxf(fabsf(radii[tid]), 0.01f);
        sraw[tid] = make_float4(cx, cy, cz, r);
        float c2 = cx * cx + cy * cy + cz * cz;
        int j = tid >> 1, h = tid & 1;
        float* a = (float*)&sA[j];
        float* b = (float*)&sB[j];
        a[0 + h] = -2.0f * cx;  a[2 + h] = -2.0f * cy;
        b[0 + h] = -2.0f * cz;  b[2 + h] = c2;
    }
    __syncthreads();
    if (tid == 0) {
        float r0 = sraw[0].w;
        int u = 1;
        float mc = 0.0f;
        #pragma unroll
        for (int e = 0; e < NEXP; e++) {
            u &= (sraw[e].w == r0);
            float4 c = sraw[e];
            mc = fmaxf(mc, c.x * c.x + c.y * c.y + c.z * c.z);
        }
        s_uniform = u;
        s_maxc2   = mc;
    }
    __syncthreads();
    const int   uniform = s_uniform;
    const float maxc2   = s_maxc2;

    // ---- phase 1: argmax per row; packed f32x2 dot fast path ----
    // uniform radii => logit order == reverse d2 order == order of
    // s = -2 p.c + |c|^2 (|p|^2 is row-constant).
    const long long gpos = (long long)blockIdx.x * TPB + tid;
    int id = 0;
    if (gpos < B) {
        const float px = pos[3 * gpos + 0];
        const float py = pos[3 * gpos + 1];
        const float pz = pos[3 * gpos + 2];

        unsigned long long px2, py2, pz2;
        PACK2(px2, px, px);
        PACK2(py2, py, py);
        PACK2(pz2, pz, pz);

        const ulonglong2* __restrict__ av = (const ulonglong2*)sA;
        const ulonglong2* __restrict__ bv = (const ulonglong2*)sB;

        float best = FLT_MAX, best2 = FLT_MAX;
        #pragma unroll
        for (int j = 0; j < NEXP / 2; j++) {
            ulonglong2 a = av[j];          // (cx pair, cy pair)
            ulonglong2 b = bv[j];          // (cz pair, c2 pair)
            unsigned long long t, sp;
            FMA2(t,  pz2, b.x, b.y);
            FMA2(t,  py2, a.y, t);
            FMA2(sp, px2, a.x, t);
            float s0, s1;
            UNPACK2(s0, s1, sp);

            float mx0 = fmaxf(best, s0);
            best2 = fminf(best2, mx0);
            id    = (s0 < best) ? 2 * j : id;
            best  = fminf(best, s0);

            float mx1 = fmaxf(best, s1);
            best2 = fminf(best2, mx1);
            id    = (s1 < best) ? 2 * j + 1 : id;
            best  = fminf(best, s1);
        }
        float pp = __fmaf_rn(px, px, __fmaf_rn(py, py, pz * pz));
        // R9's proven margin: analytic fp32 bound ~3.6e-7*(pp+2*maxc2) with
        // >3x headroom; fallback warp rate small (R8 lesson: wide = death).
        float eps = 1.2e-6f * (pp + 2.0f * maxc2 + 1.0f);
        if ((!uniform) || (best2 - best <= eps))
            id = exact_argmax(px, py, pz, sraw);
    }
    sids[tid] = id;
    __syncthreads();

    // ---- phase 2: zero-fill + predicated scalar hot store ----
    // Thread owns quad column c4 = tid & 15 of rows row = k*16 + (tid>>4).
    // The hot element of row r (column eid) lies in this thread's quad iff
    // eid>>2 == c4 -> zero STG.128 then @p st.global.f32 from the SAME thread
    // is ordered; no extra sync. Inline-asm predication avoids BSSY/BSYNC.
    // LDS between STGs paces the store stream (R6 lesson).
    const long long rowbase = (long long)blockIdx.x * TPB;
    const int c4  = tid & 15;
    const int rb  = tid >> 4;
    float4* __restrict__ zp = (float4*)out_probs + rowbase * 16 + tid;
    float*  __restrict__ hp0 = out_probs + rowbase * NEXP + rb * NEXP;
    const float4 zero4 = make_float4(0.f, 0.f, 0.f, 0.f);

    if (rowbase + TPB <= B) {
        #pragma unroll
        for (int k = 0; k < 16; k++) {
            zp[k * TPB] = zero4;
            int eid = sids[k * 16 + rb];
            float* hp = hp0 + (long long)k * 16 * NEXP + eid;
            asm volatile(
                "{\n\t"
                ".reg .pred p;\n\t"
                ".reg .b32 q;\n\t"
                "shr.b32 q, %0, 2;\n\t"
                "setp.eq.s32 p, q, %1;\n\t"
                "@p st.global.f32 [%2], %3;\n\t"
                "}"
                :: "r"(eid), "r"(c4), "l"(hp), "f"(1.0f) : "memory");
        }
    } else {
        #pragma unroll
        for (int k = 0; k < 16; k++) {
            int row = k * 16 + rb;
            if (rowbase + row < B) {
                zp[k * TPB] = zero4;
                int eid = sids[row];
                float* hp = hp0 + (long long)k * 16 * NEXP + eid;
                asm volatile(
                    "{\n\t"
                    ".reg .pred p;\n\t"
                    ".reg .b32 q;\n\t"
                    "shr.b32 q, %0, 2;\n\t"
                    "setp.eq.s32 p, q, %1;\n\t"
                    "@p st.global.f32 [%2], %3;\n\t"
                    "}"
                    :: "r"(eid), "r"(c4), "l"(hp), "f"(1.0f) : "memory");
            }
        }
    }

    if (write_ids && gpos < B) out_ids[gpos] = (float)id;
}

extern "C" void kernel_launch(void* const* d_in, const int* in_sizes, int n_in,
                              void* d_out, int out_size)
{
    const float* pos     = (const float*)d_in[0];   // positions_3d (B,3)
    const float* centers = (const float*)d_in[1];   // centers (64,3)
    const float* radii   = (const float*)d_in[2];   // radii (64,)

    int B = in_sizes[0] / 3;
    float* out_probs = (float*)d_out;
    long long need_ids = (long long)B * (NEXP + 1);
    int write_ids = ((long long)out_size >= need_ids) ? 1 : 0;
    float* out_ids = out_probs + (long long)B * NEXP;

    int grid = (B + TPB - 1) / TPB;
    optix_route_fused<<<grid, TPB>>>(pos, centers, radii, out_probs, out_ids, B, write_ids);
}

// round 11
// speedup vs baseline: 1.7914x; 1.7914x over previous
#include <cuda_runtime.h>
#include <cuda_bf16.h>
#include <float.h>

#define NEXP 64
#define TPB  256

// Rare exact path: faithful reproduction of the reference fp32 sequence
// (sqrt logits + softmax-tie band). __noinline__ + partial unroll so it never
// inflates the main kernel's register count (R3/R10 lesson).
__device__ __noinline__ int exact_argmax(float px, float py, float pz,
                                         const float4* __restrict__ sc)
{
    float m = -FLT_MAX;
    #pragma unroll 4
    for (int e = 0; e < NEXP; e++) {
        float4 c = sc[e];
        float dx = __fsub_rn(px, c.x);
        float dy = __fsub_rn(py, c.y);
        float dz = __fsub_rn(pz, c.z);
        float d2 = __fadd_rn(__fadd_rn(__fmul_rn(dx, dx), __fmul_rn(dy, dy)),
                             __fmul_rn(dz, dz));
        float dist = __fsqrt_rn(__fadd_rn(d2, 1e-12f));
        float li   = __fmul_rn(10.0f, __fsub_rn(c.w, dist));
        if (li > m) m = li;
    }
    // softmax tie band: exp(l-m) rounds to 1.0f when (m-l) <= 2^-25, so
    // argmax(softmax) picks the FIRST index inside that band.
    const float band = 2.9802322e-8f;  // 2^-25
    #pragma unroll 4
    for (int e = 0; e < NEXP; e++) {
        float4 c = sc[e];
        float dx = __fsub_rn(px, c.x);
        float dy = __fsub_rn(py, c.y);
        float dz = __fsub_rn(pz, c.z);
        float d2 = __fadd_rn(__fadd_rn(__fmul_rn(dx, dx), __fmul_rn(dy, dy)),
                             __fmul_rn(dz, dz));
        float dist = __fsqrt_rn(__fadd_rn(d2, 1e-12f));
        float li   = __fmul_rn(10.0f, __fsub_rn(c.w, dist));
        if (__fsub_rn(m, li) <= band) return e;
    }
    return NEXP - 1;  // unreachable
}

__global__ void __launch_bounds__(TPB, 8)
optix_route_fused(const float* __restrict__ pos,
                  const float* __restrict__ centers,
                  const float* __restrict__ radii,
                  float* __restrict__ out_probs,
                  float* __restrict__ out_ids,
                  int B, int write_ids)
{
    __shared__ float4 sc[NEXP];      // (cx, cy, cz, safe_r)
    __shared__ int    sids[TPB];
    __shared__ int    s_uniform;

    const int tid = threadIdx.x;

    if (tid < NEXP) {
        float cx = centers[3 * tid + 0];
        float cy = centers[3 * tid + 1];
        float cz = centers[3 * tid + 2];
        float r  = fmaxf(fabsf(radii[tid]), 0.01f);
        sc[tid] = make_float4(cx, cy, cz, r);
    }
    __syncthreads();
    if (tid == 0) {
        float r0 = sc[0].w;
        int u = 1;
        #pragma unroll
        for (int e = 1; e < NEXP; e++) u &= (sc[e].w == r0);
        s_uniform = u;
    }
    __syncthreads();
    const int uniform = s_uniform;

    // ---- phase 1: R7's proven fast path (sub/d2, tight margin) ----
    const long long gpos = (long long)blockIdx.x * TPB + tid;
    int id = 0;
    if (gpos < B) {
        const float px = pos[3 * gpos + 0];
        const float py = pos[3 * gpos + 1];
        const float pz = pos[3 * gpos + 2];

        bool need_exact = true;
        if (uniform) {
            // uniform radii => logit order == reverse d2 order. FMA-contracted
            // d2; <=~2.4e-7 relative deviation absorbed by the margin below.
            float best = FLT_MAX, best2 = FLT_MAX;
            #pragma unroll
            for (int e = 0; e < NEXP; e++) {
                float4 c = sc[e];
                float dx = px - c.x;
                float dy = py - c.y;
                float dz = pz - c.z;
                float d2 = __fmaf_rn(dx, dx, __fmaf_rn(dy, dy, dz * dz));
                float mx = fmaxf(best, d2);
                best2 = fminf(best2, mx);
                id    = (d2 < best) ? e : id;
                best  = fminf(best, d2);
            }
            need_exact = (best2 - best <= __fmaf_rn(best, 2e-6f, 1e-9f));
        }
        if (need_exact) id = exact_argmax(px, py, pz, sc);
    }
    sids[tid] = id;
    __syncthreads();

    // ---- phase 2: zero-fill + predicated scalar hot store ----
    // Thread owns quad column c4 = tid & 15 of rows row = k*16 + (tid>>4).
    // Row r's hot element (column eid) lies in this thread's quad iff
    // eid>>2 == c4, so "STG.128 zero then @p st.global.f32 1.0f" from the
    // SAME thread is ordered; no extra sync. Inline-asm predication avoids
    // BSSY/BSYNC; the LDS between STGs paces the store stream (R6 lesson).
    const long long rowbase = (long long)blockIdx.x * TPB;
    const int c4  = tid & 15;
    const int rb  = tid >> 4;
    float4* __restrict__ zp  = (float4*)out_probs + rowbase * 16 + tid;
    float*  __restrict__ hp0 = out_probs + rowbase * NEXP + (long long)rb * NEXP;
    const float4 zero4 = make_float4(0.f, 0.f, 0.f, 0.f);

    if (rowbase + TPB <= B) {
        #pragma unroll
        for (int k = 0; k < 16; k++) {
            zp[k * TPB] = zero4;
            int eid = sids[k * 16 + rb];
            float* hp = hp0 + (long long)k * 16 * NEXP + eid;
            asm volatile(
                "{\n\t"
                ".reg .pred p;\n\t"
                ".reg .b32 q;\n\t"
                "shr.b32 q, %0, 2;\n\t"
                "setp.eq.s32 p, q, %1;\n\t"
                "@p st.global.f32 [%2], %3;\n\t"
                "}"
                :: "r"(eid), "r"(c4), "l"(hp), "f"(1.0f) : "memory");
        }
    } else {
        #pragma unroll
        for (int k = 0; k < 16; k++) {
            int row = k * 16 + rb;
            if (rowbase + row < B) {
                zp[k * TPB] = zero4;
                int eid = sids[row];
                float* hp = hp0 + (long long)k * 16 * NEXP + eid;
                asm volatile(
                    "{\n\t"
                    ".reg .pred p;\n\t"
                    ".reg .b32 q;\n\t"
                    "shr.b32 q, %0, 2;\n\t"
                    "setp.eq.s32 p, q, %1;\n\t"
                    "@p st.global.f32 [%2], %3;\n\t"
                    "}"
                    :: "r"(eid), "r"(c4), "l"(hp), "f"(1.0f) : "memory");
            }
        }
    }

    if (write_ids && gpos < B) out_ids[gpos] = (float)id;
}

extern "C" void kernel_launch(void* const* d_in, const int* in_sizes, int n_in,
                              void* d_out, int out_size)
{
    const float* pos     = (const float*)d_in[0];   // positions_3d (B,3)
    const float* centers = (const float*)d_in[1];   // centers (64,3)
    const float* radii   = (const float*)d_in[2];   // radii (64,)

    int B = in_sizes[0] / 3;
    float* out_probs = (float*)d_out;
    long long need_ids = (long long)B * (NEXP + 1);
    int write_ids = ((long long)out_size >= need_ids) ? 1 : 0;
    float* out_ids = out_probs + (long long)B * NEXP;

    int grid = (B + TPB - 1) / TPB;
    optix_route_fused<<<grid, TPB>>>(pos, centers, radii, out_probs, out_ids, B, write_ids);
}

// round 12
// speedup vs baseline: 1.9705x; 1.1000x over previous
#include <cuda_runtime.h>
#include <cuda_bf16.h>
#include <float.h>

#define NEXP 64
#define TPB  256

// Rare exact path: faithful reproduction of the reference fp32 sequence
// (sqrt logits + softmax-tie band). __noinline__ + partial unroll so it never
// inflates the main kernel's register count (R3/R10 lesson).
__device__ __noinline__ int exact_argmax(float px, float py, float pz,
                                         const float4* __restrict__ sc)
{
    float m = -FLT_MAX;
    #pragma unroll 4
    for (int e = 0; e < NEXP; e++) {
        float4 c = sc[e];
        float dx = __fsub_rn(px, c.x);
        float dy = __fsub_rn(py, c.y);
        float dz = __fsub_rn(pz, c.z);
        float d2 = __fadd_rn(__fadd_rn(__fmul_rn(dx, dx), __fmul_rn(dy, dy)),
                             __fmul_rn(dz, dz));
        float dist = __fsqrt_rn(__fadd_rn(d2, 1e-12f));
        float li   = __fmul_rn(10.0f, __fsub_rn(c.w, dist));
        if (li > m) m = li;
    }
    // softmax tie band: exp(l-m) rounds to 1.0f when (m-l) <= 2^-25, so
    // argmax(softmax) picks the FIRST index inside that band.
    const float band = 2.9802322e-8f;  // 2^-25
    #pragma unroll 4
    for (int e = 0; e < NEXP; e++) {
        float4 c = sc[e];
        float dx = __fsub_rn(px, c.x);
        float dy = __fsub_rn(py, c.y);
        float dz = __fsub_rn(pz, c.z);
        float d2 = __fadd_rn(__fadd_rn(__fmul_rn(dx, dx), __fmul_rn(dy, dy)),
                             __fmul_rn(dz, dz));
        float dist = __fsqrt_rn(__fadd_rn(d2, 1e-12f));
        float li   = __fmul_rn(10.0f, __fsub_rn(c.w, dist));
        if (__fsub_rn(m, li) <= band) return e;
    }
    return NEXP - 1;  // unreachable
}

__global__ void __launch_bounds__(TPB, 8)
optix_route_fused(const float* __restrict__ pos,
                  const float* __restrict__ centers,
                  const float* __restrict__ radii,
                  float* __restrict__ out_probs,
                  float* __restrict__ out_ids,
                  int B, int write_ids)
{
    __shared__ float4 sc[NEXP];      // (cx, cy, cz, safe_r)
    __shared__ int    s_uniform;

    const int tid  = threadIdx.x;
    const int lane = tid & 31;
    const int wid  = tid >> 5;

    if (tid < NEXP) {
        float cx = centers[3 * tid + 0];
        float cy = centers[3 * tid + 1];
        float cz = centers[3 * tid + 2];
        float r  = fmaxf(fabsf(radii[tid]), 0.01f);
        sc[tid] = make_float4(cx, cy, cz, r);
    }
    __syncthreads();
    if (tid == 0) {
        float r0 = sc[0].w;
        int u = 1;
        #pragma unroll
        for (int e = 1; e < NEXP; e++) u &= (sc[e].w == r0);
        s_uniform = u;
    }
    __syncthreads();   // the ONLY barrier: sc + s_uniform ready
    const int uniform = s_uniform;

    // ---- phase 1: R7's proven fast path (sub/d2, tight margin) ----
    const long long gpos = (long long)blockIdx.x * TPB + tid;
    int id = 0;
    if (gpos < B) {
        const float px = pos[3 * gpos + 0];
        const float py = pos[3 * gpos + 1];
        const float pz = pos[3 * gpos + 2];

        bool need_exact = true;
        if (uniform) {
            // uniform radii => logit order == reverse d2 order. FMA-contracted
            // d2; <=~2.4e-7 relative deviation absorbed by the margin below.
            float best = FLT_MAX, best2 = FLT_MAX;
            #pragma unroll
            for (int e = 0; e < NEXP; e++) {
                float4 c = sc[e];
                float dx = px - c.x;
                float dy = py - c.y;
                float dz = pz - c.z;
                float d2 = __fmaf_rn(dx, dx, __fmaf_rn(dy, dy, dz * dz));
                float mx = fmaxf(best, d2);
                best2 = fminf(best2, mx);
                id    = (d2 < best) ? e : id;
                best  = fminf(best, d2);
            }
            need_exact = (best2 - best <= __fmaf_rn(best, 2e-6f, 1e-9f));
        }
        if (need_exact) id = exact_argmax(px, py, pz, sc);

        if (write_ids) out_ids[gpos] = (float)id;
    }

    // ---- phase 2: barrier-free warp-local one-hot emission ----
    // This warp owns rows [warprow, warprow+32). float4 slot k*32+lane maps to
    // local row 2k + (lane>>4); its id comes from a shuffle within THIS warp.
    // No __syncthreads, no shared sids: warps stream independently, so a slow
    // exact-path warp no longer stalls its whole block. SHFL between STG.128s
    // paces the store stream (R6 lesson).
    const long long warprow = (long long)blockIdx.x * TPB + wid * 32;
    float4* __restrict__ wp = (float4*)out_probs + warprow * 16 + lane;
    const int c4b = (lane & 15) << 2;            // first column of my quad
    const int rsel = lane >> 4;                  // 0 or 1: which row of the pair

    if (warprow + 32 <= B) {
        #pragma unroll
        for (int k = 0; k < 16; k++) {
            int eid = __shfl_sync(0xffffffffu, id, 2 * k + rsel);
            int t = eid - c4b;
            float4 v;
            v.x = (t == 0) ? 1.0f : 0.0f;
            v.y = (t == 1) ? 1.0f : 0.0f;
            v.z = (t == 2) ? 1.0f : 0.0f;
            v.w = (t == 3) ? 1.0f : 0.0f;
            wp[k * 32] = v;
        }
    } else {
        #pragma unroll
        for (int k = 0; k < 16; k++) {
            int eid = __shfl_sync(0xffffffffu, id, 2 * k + rsel);
            if (warprow + 2 * k + rsel < B) {
                int t = eid - c4b;
                float4 v;
                v.x = (t == 0) ? 1.0f : 0.0f;
                v.y = (t == 1) ? 1.0f : 0.0f;
                v.z = (t == 2) ? 1.0f : 0.0f;
                v.w = (t == 3) ? 1.0f : 0.0f;
                wp[k * 32] = v;
            }
        }
    }
}

extern "C" void kernel_launch(void* const* d_in, const int* in_sizes, int n_in,
                              void* d_out, int out_size)
{
    const float* pos     = (const float*)d_in[0];   // positions_3d (B,3)
    const float* centers = (const float*)d_in[1];   // centers (64,3)
    const float* radii   = (const float*)d_in[2];   // radii (64,)

    int B = in_sizes[0] / 3;
    float* out_probs = (float*)d_out;
    long long need_ids = (long long)B * (NEXP + 1);
    int write_ids = ((long long)out_size >= need_ids) ? 1 : 0;
    float* out_ids = out_probs + (long long)B * NEXP;

    int grid = (B + TPB - 1) / TPB;
    optix_route_fused<<<grid, TPB>>>(pos, centers, radii, out_probs, out_ids, B, write_ids);
}